// round 10
// baseline (speedup 1.0000x reference)
#include <cuda_runtime.h>
#include <math.h>

// Problem shape (fixed by the reference)
#define BB   32
#define CC   256
#define HH   128
#define WW   128
#define HWSZ (HH * WW)       // 16384
#define HW4  (HWSZ / 4)      // 4096 float4 per (b) spatial plane
#define TPB  128             // 128-thread CTAs (R9-proven granularity)
#define CHUNKS (HW4 / TPB)   // 32 CTAs per batch plane

// Scratch (allocation-free: __device__ globals). 2 * 2 MiB, L2-resident.
__device__ float g_avg[BB * HWSZ];
__device__ float g_max[BB * HWSZ];
__device__ unsigned int g_cnt[BB];   // per-batch arrival counters

// ---------------------------------------------------------------------------
// Kernel 0: zero the per-batch counters (deterministic per replay).
// ---------------------------------------------------------------------------
__global__ void zero_counters() {
    if (threadIdx.x < BB) g_cnt[threadIdx.x] = 0u;
}

// ---------------------------------------------------------------------------
// Fused kernel: reduce -> per-batch software barrier -> conv gate -> apply.
// grid (32, 32) = 1024 CTAs x 128 thr: ALL wave-1 resident
// (148 SMs x 7 CTAs = 1036 slots; 64 regs * 128 thr * 7 = 57344 <= 64K regs),
// so the per-batch spin-wait cannot deadlock.
//
// Phase 1 (reduce): this CTA's 128 float4 columns of batch b, over C=256,
//   unroll 8 (R4-proven read config). Publish avg/max, arrive on g_cnt[b].
// Phase 2 (barrier): thread 0 spins with __nanosleep until all 32 chunk-CTAs
//   of batch b arrived (store -> bar -> fence -> atomicAdd release pattern;
//   atomicAdd(,0) poll + fence acquire on the wait side).
// Phase 3 (gate + apply): R9-proven conv prologue (3x3x2 correlation, zero
//   pad, sigmoid; conv_w [1,2,3,3] row-major = correlation for NCHW/OIHW)
//   and unroll-4 apply loop (proven best MLP for the mixed R/W stream).
// ---------------------------------------------------------------------------
__global__ __launch_bounds__(TPB, 8) void fused_attn(const float* __restrict__ x,
                                                     const float* __restrict__ y,
                                                     const float* __restrict__ cw,
                                                     float* __restrict__ out) {
    const int b  = blockIdx.y;
    const int t4 = blockIdx.x * TPB + threadIdx.x;   // float4 index in plane

    // ---- Phase 1: channel reduce for own chunk --------------------------
    {
        const float4* yp = reinterpret_cast<const float4*>(y)
                         + (size_t)b * CC * HW4 + t4;

        float4 s = make_float4(0.f, 0.f, 0.f, 0.f);
        float4 m = make_float4(-INFINITY, -INFINITY, -INFINITY, -INFINITY);

        #pragma unroll 8
        for (int c = 0; c < CC; ++c) {
            float4 v = yp[(size_t)c * HW4];
            s.x += v.x; s.y += v.y; s.z += v.z; s.w += v.w;
            m.x = fmaxf(m.x, v.x); m.y = fmaxf(m.y, v.y);
            m.z = fmaxf(m.z, v.z); m.w = fmaxf(m.w, v.w);
        }

        const float inv = 1.0f / (float)CC;
        float4 a = make_float4(s.x * inv, s.y * inv, s.z * inv, s.w * inv);

        reinterpret_cast<float4*>(g_avg)[(size_t)b * HW4 + t4] = a;
        reinterpret_cast<float4*>(g_max)[(size_t)b * HW4 + t4] = m;
    }

    // ---- Phase 2: per-batch software barrier ----------------------------
    __syncthreads();                       // all CTA stores issued
    if (threadIdx.x == 0) {
        __threadfence();                   // release: publish avg/max
        atomicAdd(&g_cnt[b], 1u);
        while (atomicAdd(&g_cnt[b], 0u) < (unsigned)CHUNKS)
            __nanosleep(200);
        __threadfence();                   // acquire: see peers' avg/max
    }
    __syncthreads();

    // ---- Phase 3a: gate prologue ----------------------------------------
    const int p0 = t4 * 4;                 // first pixel index
    const int h  = p0 >> 7;                // row (4 px share a row)
    const int w0 = p0 & (WW - 1);          // first col (0..124)

    float wt[18];
    #pragma unroll
    for (int i = 0; i < 18; ++i) wt[i] = __ldg(&cw[i]);

    float A[3][6], M[3][6];
    #pragma unroll
    for (int r = 0; r < 3; ++r) {
        const int hh = h - 1 + r;
        const bool hv = (hh >= 0) && (hh < HH);
        #pragma unroll
        for (int cc = 0; cc < 6; ++cc) {
            const int ww = w0 - 1 + cc;
            const bool v = hv && (ww >= 0) && (ww < WW);
            const int off = b * HWSZ + hh * WW + ww;
            A[r][cc] = v ? g_avg[off] : 0.0f;   // plain loads (fresh, post-barrier)
            M[r][cc] = v ? g_max[off] : 0.0f;
        }
    }

    float4 g;
    float* gp = &g.x;
    #pragma unroll
    for (int i = 0; i < 4; ++i) {
        float acc = 0.0f;
        #pragma unroll
        for (int r = 0; r < 3; ++r) {
            #pragma unroll
            for (int dj = 0; dj < 3; ++dj) {
                const int k = r * 3 + dj;
                acc = fmaf(A[r][i + dj], wt[k],     acc);
                acc = fmaf(M[r][i + dj], wt[9 + k], acc);
            }
        }
        gp[i] = 1.0f / (1.0f + expf(-acc));
    }

    // ---- Phase 3b: apply main loop (unroll 4, proven) -------------------
    const size_t base = (size_t)b * CC * HW4 + t4;
    const float4* xp = reinterpret_cast<const float4*>(x) + base;
    float4*       op = reinterpret_cast<float4*>(out)     + base;

    #pragma unroll 4
    for (int c = 0; c < CC; ++c) {
        float4 v = xp[(size_t)c * HW4];
        v.x *= g.x; v.y *= g.y; v.z *= g.z; v.w *= g.w;
        op[(size_t)c * HW4] = v;
    }
}

// ---------------------------------------------------------------------------
// Launch. Inputs (metadata order): d_in[0]=x [B,C,H,W] f32,
// d_in[1]=y [B,C,H,W] f32, d_in[2]=conv_w [1,2,3,3] f32. Output f32 [B,C,H,W].
// ---------------------------------------------------------------------------
extern "C" void kernel_launch(void* const* d_in, const int* in_sizes, int n_in,
                              void* d_out, int out_size) {
    (void)in_sizes; (void)n_in; (void)out_size;
    const float* x  = (const float*)d_in[0];
    const float* y  = (const float*)d_in[1];
    const float* cw = (const float*)d_in[2];
    float* out = (float*)d_out;

    zero_counters<<<1, 32>>>();

    dim3 grid(CHUNKS, BB);               // (32, 32) = 1024 CTAs of 128 thr
    fused_attn<<<grid, TPB>>>(x, y, cw, out);
}